// round 6
// baseline (speedup 1.0000x reference)
#include <cuda_runtime.h>
#include <math.h>

// Problem constants
#define B_   4
#define N_   8400
#define NM_  32
#define H_   160
#define W_   160
#define D_   100
#define HW_  (H_*W_)          // 25600
#define OW_  640
#define OH_  640

// Scratch: sigmoid masks [B][D][H][W] fp32 = 40.96 MB (device global scratch)
__device__ float g_S[(size_t)B_ * D_ * HW_];

// ---------------------------------------------------------------------------
// Kernel A: coeff gather + GEMM over NM=32 + sigmoid -> g_S
// grid (25, 5, 4) = (pixel tiles of 1024, d-tiles of 20, batch); block 256.
// Each thread: 4 adjacent pixels (one float4 proto load per k) x 20 d.
// ---------------------------------------------------------------------------
#define DT_  20
#define PXT_ 4

__global__ void __launch_bounds__(256, 2)
kernelA(const float* __restrict__ mc,
        const float* __restrict__ proto,
        const void* __restrict__ det)      // int32 vs int64 detected on device
{
    const int b  = blockIdx.z;
    const int d0 = blockIdx.y * DT_;
    const int p0 = blockIdx.x * (256 * PXT_) + threadIdx.x * PXT_;

    // Detect int64 vs int32: int64 values < 2^31 have all-zero odd int32 words.
    const int* d32 = (const int*)det;
    bool is64 = true;
    #pragma unroll
    for (int k = 0; k < 8; k++) if (d32[2 * k + 1] != 0) is64 = false;

    // coeffs transposed: sc[n][d]
    __shared__ float sc[NM_][DT_];
    for (int i = threadIdx.x; i < NM_ * DT_; i += 256) {
        const int n = i / DT_;
        const int d = i % DT_;
        const int flat = b * D_ + d0 + d;
        long long idx = is64 ? ((const long long*)det)[flat] : (long long)d32[flat];
        idx = min(max(idx, 0LL), (long long)(N_ - 1));   // defensive clamp
        sc[n][d] = mc[((long long)b * N_ + idx) * NM_ + n];
    }
    __syncthreads();

    float acc[DT_][4];
    #pragma unroll
    for (int d = 0; d < DT_; d++)
        #pragma unroll
        for (int j = 0; j < 4; j++) acc[d][j] = 0.f;

    const float* pbase = proto + (size_t)b * NM_ * HW_ + p0;

    #pragma unroll 4
    for (int n = 0; n < NM_; n++) {
        const float4 p = *reinterpret_cast<const float4*>(pbase + (size_t)n * HW_);
        #pragma unroll
        for (int d = 0; d < DT_; d++) {
            const float c = sc[n][d];
            acc[d][0] = fmaf(p.x, c, acc[d][0]);
            acc[d][1] = fmaf(p.y, c, acc[d][1]);
            acc[d][2] = fmaf(p.z, c, acc[d][2]);
            acc[d][3] = fmaf(p.w, c, acc[d][3]);
        }
    }

    #pragma unroll
    for (int d = 0; d < DT_; d++) {
        float4 s;
        s.x = 1.0f / (1.0f + expf(-acc[d][0]));
        s.y = 1.0f / (1.0f + expf(-acc[d][1]));
        s.z = 1.0f / (1.0f + expf(-acc[d][2]));
        s.w = 1.0f / (1.0f + expf(-acc[d][3]));
        *reinterpret_cast<float4*>(g_S + ((size_t)(b * D_ + d0 + d)) * HW_ + p0) = s;
    }
}

// ---------------------------------------------------------------------------
// Kernel B: 4x half-pixel bilinear upsample + threshold -> FLOAT32 out (0/1)
// grid (4 row-bands, 100 d, 4 b); block 256; smem band of 42 source rows.
// Row groups: output rows 4g+2..4g+5 interpolate source rows (g, g+1),
//   fy = 0.125 + 0.25k. Cols: x=4c+k uses (c-1,c) fx={0.625,0.875} for k=0,1
//   and (c,c+1) fx={0.125,0.375} for k=2,3.
// Each item = one row group x one 16-px strip (src cols 4t-1..4t+4).
// ---------------------------------------------------------------------------
__global__ void __launch_bounds__(256)
kernelB(float* __restrict__ out)
{
    const int band = blockIdx.x;           // 0..3 : output rows [160*band, +160)
    const int d    = blockIdx.y;
    const int b    = blockIdx.z;
    const int R0   = 40 * band - 1;        // first source row in smem (pre-clamp)

    __shared__ float sS[42 * 160];         // 26.9 KB (+1 halo row each side)

    const float* Sg = g_S + ((size_t)(b * D_ + d)) * HW_;
    for (int i = threadIdx.x; i < 42 * 40; i += 256) {
        const int r  = i / 40;
        const int x4 = i % 40;
        const int gr = min(max(R0 + r, 0), H_ - 1);
        *reinterpret_cast<float4*>(&sS[r * 160 + x4 * 4]) =
            *reinterpret_cast<const float4*>(Sg + gr * 160 + x4 * 4);
    }
    __syncthreads();

    float* obase = out + ((size_t)(b * D_ + d)) * (OH_ * OW_);
    const int Y0 = 160 * band;

    for (int it = threadIdx.x; it < 41 * 40; it += 256) {
        const int gl = it / 40;            // 0..40
        const int t  = it % 40;            // 16-px strip
        const int g  = R0 + gl;            // source row group

        const int sr0 = min(max(g, 0), H_ - 1) - R0;
        const int sr1 = min(g + 1, H_ - 1) - R0;
        const float* row0 = &sS[sr0 * 160];
        const float* row1 = &sS[sr1 * 160];

        const int cm = max(4 * t - 1, 0);
        const int cp = min(4 * t + 4, W_ - 1);

        float A0[6], A1[6];
        const float4 m0 = *reinterpret_cast<const float4*>(row0 + 4 * t);
        const float4 m1 = *reinterpret_cast<const float4*>(row1 + 4 * t);
        A0[0] = row0[cm]; A0[1] = m0.x; A0[2] = m0.y; A0[3] = m0.z; A0[4] = m0.w; A0[5] = row0[cp];
        A1[0] = row1[cm]; A1[1] = m1.x; A1[2] = m1.y; A1[3] = m1.z; A1[4] = m1.w; A1[5] = row1[cp];

        float h0[16], h1[16];
        #pragma unroll
        for (int q = 0; q < 4; q++) {
            const float d0a = A0[q + 1] - A0[q];
            const float d0b = A0[q + 2] - A0[q + 1];
            const float d1a = A1[q + 1] - A1[q];
            const float d1b = A1[q + 2] - A1[q + 1];
            h0[4*q + 0] = fmaf(0.625f, d0a, A0[q]);
            h0[4*q + 1] = fmaf(0.875f, d0a, A0[q]);
            h0[4*q + 2] = fmaf(0.125f, d0b, A0[q + 1]);
            h0[4*q + 3] = fmaf(0.375f, d0b, A0[q + 1]);
            h1[4*q + 0] = fmaf(0.625f, d1a, A1[q]);
            h1[4*q + 1] = fmaf(0.875f, d1a, A1[q]);
            h1[4*q + 2] = fmaf(0.125f, d1b, A1[q + 1]);
            h1[4*q + 3] = fmaf(0.375f, d1b, A1[q + 1]);
        }

        float vd[16];
        #pragma unroll
        for (int k = 0; k < 16; k++) vd[k] = h1[k] - h0[k];

        const int ybase = 4 * g + 2;
        #pragma unroll
        for (int k = 0; k < 4; k++) {
            const int y = ybase + k;
            if (y < Y0 || y >= Y0 + 160) continue;   // row owned by another band
            const float fy = 0.125f + 0.25f * (float)k;
            float* orow = obase + (size_t)y * OW_ + 16 * t;
            #pragma unroll
            for (int q4 = 0; q4 < 4; q4++) {
                float4 o;
                o.x = (fmaf(fy, vd[4*q4 + 0], h0[4*q4 + 0]) > 0.5f) ? 1.0f : 0.0f;
                o.y = (fmaf(fy, vd[4*q4 + 1], h0[4*q4 + 1]) > 0.5f) ? 1.0f : 0.0f;
                o.z = (fmaf(fy, vd[4*q4 + 2], h0[4*q4 + 2]) > 0.5f) ? 1.0f : 0.0f;
                o.w = (fmaf(fy, vd[4*q4 + 3], h0[4*q4 + 3]) > 0.5f) ? 1.0f : 0.0f;
                *reinterpret_cast<float4*>(orow + 4 * q4) = o;
            }
        }
    }
}

// ---------------------------------------------------------------------------
extern "C" void kernel_launch(void* const* d_in, const int* in_sizes, int n_in,
                              void* d_out, int out_size)
{
    // Binding robust to order and units (elements or bytes):
    //   det << mc < proto, all strictly distinct.
    const float* mc    = nullptr;
    const float* proto = nullptr;
    const void*  det   = nullptr;

    for (int i = 0; i < n_in; i++) {
        const long long s = in_sizes[i];
        if      (s == 1075200LL || s == 4300800LL)                        mc    = (const float*)d_in[i];
        else if (s == 3276800LL || s == 13107200LL)                       proto = (const float*)d_in[i];
        else if (s == 400LL || s == 800LL || s == 1600LL || s == 3200LL)  det   = d_in[i];
    }
    if (!mc || !proto || !det) {   // rank fallback among first 3
        int imin = 0, imax = 0;
        for (int i = 1; i < 3 && i < n_in; i++) {
            if (in_sizes[i] < in_sizes[imin]) imin = i;
            if (in_sizes[i] > in_sizes[imax]) imax = i;
        }
        const int imid = 3 - imin - imax;
        det   = d_in[imin];
        proto = (const float*)d_in[imax];
        mc    = (const float*)d_in[imid];
    }

    float* out = (float*)d_out;     // [4,100,640,640] FLOAT32 (0.0 / 1.0)
    (void)out_size;

    kernelA<<<dim3(HW_ / (256 * PXT_), D_ / DT_, B_), 256>>>(mc, proto, det);
    kernelB<<<dim3(4, D_, B_), 256>>>(out);
}

// round 7
// speedup vs baseline: 1.0045x; 1.0045x over previous
#include <cuda_runtime.h>
#include <math.h>
#include <stdint.h>

// Problem constants
#define B_   4
#define N_   8400
#define NM_  32
#define H_   160
#define W_   160
#define D_   100
#define HW_  (H_*W_)          // 25600
#define OW_  640
#define OH_  640

// Scratch: sigmoid masks [B][D][H][W] fp32 = 40.96 MB
__device__ float g_S[(size_t)B_ * D_ * HW_];

// Packed fp32x2 FMA (Blackwell FFMA2) — PTX-only
__device__ __forceinline__ float2 ffma2(float2 a, float2 b, float2 c) {
    union { float2 f; unsigned long long u; } ua, ub, uc, ur;
    ua.f = a; ub.f = b; uc.f = c;
    asm("fma.rn.f32x2 %0, %1, %2, %3;" : "=l"(ur.u) : "l"(ua.u), "l"(ub.u), "l"(uc.u));
    return ur.f;
}

// ---------------------------------------------------------------------------
// Kernel A: coeff gather + GEMM over NM=32 + sigmoid -> g_S
// grid (25, 5, 4); block 256. Each thread: 4 adjacent px x 20 d.
// ---------------------------------------------------------------------------
#define DT_  20
#define PXT_ 4

__global__ void __launch_bounds__(256, 2)
kernelA(const float* __restrict__ mc,
        const float* __restrict__ proto,
        const void* __restrict__ det)      // int32 vs int64 detected on device
{
    const int b  = blockIdx.z;
    const int d0 = blockIdx.y * DT_;
    const int p0 = blockIdx.x * (256 * PXT_) + threadIdx.x * PXT_;

    // int64 det values < 2^31 -> all odd int32 words zero
    const int* d32 = (const int*)det;
    bool is64 = true;
    #pragma unroll
    for (int k = 0; k < 8; k++) if (d32[2 * k + 1] != 0) is64 = false;

    __shared__ float sc[NM_][DT_];
    for (int i = threadIdx.x; i < NM_ * DT_; i += 256) {
        const int n = i / DT_;
        const int d = i % DT_;
        const int flat = b * D_ + d0 + d;
        long long idx = is64 ? ((const long long*)det)[flat] : (long long)d32[flat];
        idx = min(max(idx, 0LL), (long long)(N_ - 1));
        sc[n][d] = mc[((long long)b * N_ + idx) * NM_ + n];
    }
    __syncthreads();

    float2 acc[DT_][2];
    #pragma unroll
    for (int d = 0; d < DT_; d++) {
        acc[d][0] = make_float2(0.f, 0.f);
        acc[d][1] = make_float2(0.f, 0.f);
    }

    const float* pbase = proto + (size_t)b * NM_ * HW_ + p0;

    #pragma unroll 4
    for (int n = 0; n < NM_; n++) {
        const float4 p = *reinterpret_cast<const float4*>(pbase + (size_t)n * HW_);
        const float2 pa = make_float2(p.x, p.y);
        const float2 pb = make_float2(p.z, p.w);
        #pragma unroll
        for (int d = 0; d < DT_; d++) {
            const float c = sc[n][d];
            const float2 cc = make_float2(c, c);
            acc[d][0] = ffma2(pa, cc, acc[d][0]);
            acc[d][1] = ffma2(pb, cc, acc[d][1]);
        }
    }

    #pragma unroll
    for (int d = 0; d < DT_; d++) {
        float4 s;
        s.x = 1.0f / (1.0f + expf(-acc[d][0].x));
        s.y = 1.0f / (1.0f + expf(-acc[d][0].y));
        s.z = 1.0f / (1.0f + expf(-acc[d][1].x));
        s.w = 1.0f / (1.0f + expf(-acc[d][1].y));
        *reinterpret_cast<float4*>(g_S + ((size_t)(b * D_ + d0 + d)) * HW_ + p0) = s;
    }
}

// ---------------------------------------------------------------------------
// Kernel B: 4x bilinear upsample + threshold, staged in smem, TMA bulk store.
// grid (4 bands, 100 d, 4 b); block 256; dynamic smem = band(26.9K)+stage(50K).
// Band: output rows [160*band, +160) of one (b,d) image (gmem-contiguous).
// 8 chunks of 20 output rows; per chunk: compute into stage, bulk-copy out.
// ---------------------------------------------------------------------------
#define CHUNK_ROWS 20
#define STAGE_FLOATS (CHUNK_ROWS * OW_)        // 12800 floats = 51200 B
#define BAND_FLOATS  (42 * 160)                // 6720 floats  = 26880 B
#define SMEMB_BYTES  ((BAND_FLOATS + STAGE_FLOATS) * 4)

__global__ void __launch_bounds__(256)
kernelB(float* __restrict__ out)
{
    extern __shared__ float smem[];
    float* sS    = smem;                 // [42][160] source band (+halo)
    float* stage = smem + BAND_FLOATS;   // [20][640] output staging

    const int band = blockIdx.x;
    const int d    = blockIdx.y;
    const int b    = blockIdx.z;
    const int R0   = 40 * band - 1;      // first source row in smem (pre-clamp)
    const int Y0   = 160 * band;

    // load source band
    const float* Sg = g_S + ((size_t)(b * D_ + d)) * HW_;
    for (int i = threadIdx.x; i < 42 * 40; i += 256) {
        const int r  = i / 40;
        const int x4 = i % 40;
        const int gr = min(max(R0 + r, 0), H_ - 1);
        *reinterpret_cast<float4*>(&sS[r * 160 + x4 * 4]) =
            *reinterpret_cast<const float4*>(Sg + gr * 160 + x4 * 4);
    }
    __syncthreads();

    char* gout = (char*)(out + ((size_t)(b * D_ + d)) * (OH_ * OW_) + (size_t)Y0 * OW_);
    const uint32_t stage_s = (uint32_t)__cvta_generic_to_shared(stage);

    for (int ci = 0; ci < 8; ci++) {
        const int yc0 = Y0 + ci * CHUNK_ROWS;

        // 800 items: (local row ry 0..19) x (16-px strip t 0..39)
        for (int it = threadIdx.x; it < CHUNK_ROWS * 40; it += 256) {
            const int ry = it / 40;
            const int t  = it % 40;
            const int y  = yc0 + ry;

            const int yy = y - 2;
            const int g  = (yy >= 0) ? (yy >> 2) : -1;
            const int k  = yy - 4 * g;
            const float fy = 0.125f + 0.25f * (float)k;

            const int sr0 = min(max(g, 0), H_ - 1) - R0;
            const int sr1 = min(g + 1, H_ - 1) - R0;
            const float* row0 = &sS[sr0 * 160];
            const float* row1 = &sS[sr1 * 160];

            const int cm = max(4 * t - 1, 0);
            const int cp = min(4 * t + 4, W_ - 1);

            // 6 taps per row, vertical lerp first (separable bilinear)
            float V[6];
            {
                const float4 m0 = *reinterpret_cast<const float4*>(row0 + 4 * t);
                const float4 m1 = *reinterpret_cast<const float4*>(row1 + 4 * t);
                const float a0 = row0[cm], a5 = row0[cp];
                const float b0 = row1[cm], b5 = row1[cp];
                V[0] = fmaf(fy, b0 - a0, a0);
                V[1] = fmaf(fy, m1.x - m0.x, m0.x);
                V[2] = fmaf(fy, m1.y - m0.y, m0.y);
                V[3] = fmaf(fy, m1.z - m0.z, m0.z);
                V[4] = fmaf(fy, m1.w - m0.w, m0.w);
                V[5] = fmaf(fy, b5 - a5, a5);
            }

            float* srow = &stage[ry * OW_ + 16 * t];
            #pragma unroll
            for (int q = 0; q < 4; q++) {
                const float da = V[q + 1] - V[q];
                const float db = V[q + 2] - V[q + 1];
                float4 o;
                o.x = (fmaf(0.625f, da, V[q])     > 0.5f) ? 1.0f : 0.0f;
                o.y = (fmaf(0.875f, da, V[q])     > 0.5f) ? 1.0f : 0.0f;
                o.z = (fmaf(0.125f, db, V[q + 1]) > 0.5f) ? 1.0f : 0.0f;
                o.w = (fmaf(0.375f, db, V[q + 1]) > 0.5f) ? 1.0f : 0.0f;
                *reinterpret_cast<float4*>(srow + 4 * q) = o;
            }
        }
        __syncthreads();

        if (threadIdx.x == 0) {
            asm volatile("fence.proxy.async.shared::cta;" ::: "memory");
            asm volatile("cp.async.bulk.global.shared::cta.bulk_group [%0], [%1], %2;"
                         :: "l"(gout + (size_t)ci * (STAGE_FLOATS * 4)),
                            "r"(stage_s), "r"((uint32_t)(STAGE_FLOATS * 4))
                         : "memory");
            asm volatile("cp.async.bulk.commit_group;" ::: "memory");
            // buffer reusable as soon as TMA has READ smem; writes drain async
            asm volatile("cp.async.bulk.wait_group.read 0;" ::: "memory");
        }
        __syncthreads();
    }
}

// ---------------------------------------------------------------------------
extern "C" void kernel_launch(void* const* d_in, const int* in_sizes, int n_in,
                              void* d_out, int out_size)
{
    // Size-based binding (robust to order/units): det << mc < proto
    const float* mc    = nullptr;
    const float* proto = nullptr;
    const void*  det   = nullptr;

    for (int i = 0; i < n_in; i++) {
        const long long s = in_sizes[i];
        if      (s == 1075200LL || s == 4300800LL)                        mc    = (const float*)d_in[i];
        else if (s == 3276800LL || s == 13107200LL)                       proto = (const float*)d_in[i];
        else if (s == 400LL || s == 800LL || s == 1600LL || s == 3200LL)  det   = d_in[i];
    }
    if (!mc || !proto || !det) {
        int imin = 0, imax = 0;
        for (int i = 1; i < 3 && i < n_in; i++) {
            if (in_sizes[i] < in_sizes[imin]) imin = i;
            if (in_sizes[i] > in_sizes[imax]) imax = i;
        }
        const int imid = 3 - imin - imax;
        det   = d_in[imin];
        proto = (const float*)d_in[imax];
        mc    = (const float*)d_in[imid];
    }

    float* out = (float*)d_out;     // [4,100,640,640] f32 (0.0/1.0)
    (void)out_size;

    cudaFuncSetAttribute(kernelB, cudaFuncAttributeMaxDynamicSharedMemorySize, SMEMB_BYTES);

    kernelA<<<dim3(HW_ / (256 * PXT_), D_ / DT_, B_), 256>>>(mc, proto, det);
    kernelB<<<dim3(4, D_, B_), 256, SMEMB_BYTES>>>(out);
}

// round 8
// speedup vs baseline: 1.4399x; 1.4334x over previous
#include <cuda_runtime.h>
#include <math.h>
#include <stdint.h>

// Problem constants
#define B_   4
#define N_   8400
#define NM_  32
#define H_   160
#define W_   160
#define D_   100
#define HW_  (H_*W_)          // 25600
#define OW_  640
#define OH_  640

// Scratch: sigmoid masks [B][D][H][W] fp32 = 40.96 MB
__device__ float g_S[(size_t)B_ * D_ * HW_];

// Packed fp32x2 FMA (Blackwell FFMA2) — PTX-only
__device__ __forceinline__ float2 ffma2(float2 a, float2 b, float2 c) {
    union { float2 f; unsigned long long u; } ua, ub, uc, ur;
    ua.f = a; ub.f = b; uc.f = c;
    asm("fma.rn.f32x2 %0, %1, %2, %3;" : "=l"(ur.u) : "l"(ua.u), "l"(ub.u), "l"(uc.u));
    return ur.f;
}

// ---------------------------------------------------------------------------
// Kernel A: coeff gather + GEMM over NM=32 + sigmoid -> g_S
// grid (25, 10, 4); block 256; 3 CTAs/SM. Thread: 4 adjacent px x 10 d.
// ---------------------------------------------------------------------------
#define DT_  10
#define PXT_ 4

__global__ void __launch_bounds__(256, 3)
kernelA(const float* __restrict__ mc,
        const float* __restrict__ proto,
        const void* __restrict__ det)      // int32 vs int64 detected on device
{
    const int b  = blockIdx.z;
    const int d0 = blockIdx.y * DT_;
    const int p0 = blockIdx.x * (256 * PXT_) + threadIdx.x * PXT_;

    // int64 det values < 2^31 -> all odd int32 words zero
    const int* d32 = (const int*)det;
    bool is64 = true;
    #pragma unroll
    for (int k = 0; k < 8; k++) if (d32[2 * k + 1] != 0) is64 = false;

    __shared__ float sc[NM_][DT_];
    for (int i = threadIdx.x; i < NM_ * DT_; i += 256) {
        const int n = i / DT_;
        const int d = i % DT_;
        const int flat = b * D_ + d0 + d;
        long long idx = is64 ? ((const long long*)det)[flat] : (long long)d32[flat];
        idx = min(max(idx, 0LL), (long long)(N_ - 1));
        sc[n][d] = mc[((long long)b * N_ + idx) * NM_ + n];
    }
    __syncthreads();

    float2 acc[DT_][2];
    #pragma unroll
    for (int d = 0; d < DT_; d++) {
        acc[d][0] = make_float2(0.f, 0.f);
        acc[d][1] = make_float2(0.f, 0.f);
    }

    const float* pbase = proto + (size_t)b * NM_ * HW_ + p0;

    #pragma unroll 8
    for (int n = 0; n < NM_; n++) {
        const float4 p = *reinterpret_cast<const float4*>(pbase + (size_t)n * HW_);
        const float2 pa = make_float2(p.x, p.y);
        const float2 pb = make_float2(p.z, p.w);
        #pragma unroll
        for (int d = 0; d < DT_; d++) {
            const float c = sc[n][d];
            const float2 cc = make_float2(c, c);
            acc[d][0] = ffma2(pa, cc, acc[d][0]);
            acc[d][1] = ffma2(pb, cc, acc[d][1]);
        }
    }

    #pragma unroll
    for (int d = 0; d < DT_; d++) {
        float4 s;
        s.x = 1.0f / (1.0f + expf(-acc[d][0].x));
        s.y = 1.0f / (1.0f + expf(-acc[d][0].y));
        s.z = 1.0f / (1.0f + expf(-acc[d][1].x));
        s.w = 1.0f / (1.0f + expf(-acc[d][1].y));
        *reinterpret_cast<float4*>(g_S + ((size_t)(b * D_ + d0 + d)) * HW_ + p0) = s;
    }
}

// ---------------------------------------------------------------------------
// Kernel B: 4x bilinear upsample + threshold; per-warp row pipelines with
// per-row TMA bulk stores (double-buffered, wait_group.read 1). No block
// barriers after the band load -> continuous DRAM write stream.
// grid (4 bands, 100 d, 4 b); block 256 (8 warps); smem 66.3 KB -> 3 CTAs/SM.
// Warp w handles output rows Y0 + w + 8*ri, ri = 0..19.
// ---------------------------------------------------------------------------
#define BAND_FLOATS  (42 * 160)                          // 6720 floats
#define ROW_FLOATS   OW_                                 // 640 floats = 2560 B
#define SMEMB_BYTES  ((BAND_FLOATS + 8 * 2 * ROW_FLOATS) * 4)   // 67840 B

__global__ void __launch_bounds__(256)
kernelB(float* __restrict__ out)
{
    extern __shared__ float smem[];
    float* sS = smem;                                    // [42][160] band

    const int band = blockIdx.x;
    const int d    = blockIdx.y;
    const int b    = blockIdx.z;
    const int R0   = 40 * band - 1;                      // first band source row
    const int Y0   = 160 * band;

    // load source band (smem row r holds global row clamp(R0 + r))
    const float* Sg = g_S + ((size_t)(b * D_ + d)) * HW_;
    for (int i = threadIdx.x; i < 42 * 40; i += 256) {
        const int r  = i / 40;
        const int x4 = i % 40;
        const int gr = min(max(R0 + r, 0), H_ - 1);
        *reinterpret_cast<float4*>(&sS[r * 160 + x4 * 4]) =
            *reinterpret_cast<const float4*>(Sg + gr * 160 + x4 * 4);
    }
    __syncthreads();

    const int w    = threadIdx.x >> 5;
    const int lane = threadIdx.x & 31;
    float* wstage = smem + BAND_FLOATS + w * (2 * ROW_FLOATS);
    const char* gbase = (const char*)(out + ((size_t)(b * D_ + d)) * (OH_ * OW_));

    for (int ri = 0; ri < 20; ri++) {
        const int y   = Y0 + w + 8 * ri;
        const int buf = ri & 1;
        float* srow = wstage + buf * ROW_FLOATS;

        // before overwriting this buffer, ensure TMA finished READING it
        if (ri >= 2) {
            if (lane == 0)
                asm volatile("cp.async.bulk.wait_group.read 1;" ::: "memory");
        }
        __syncwarp();

        const int yy = y - 2;
        const int g  = (yy >= 0) ? (yy >> 2) : -1;
        const int k  = yy - 4 * g;
        const float fy = 0.125f + 0.25f * (float)k;

        const float* row0 = &sS[(min(max(g, 0),     H_ - 1) - R0) * 160];
        const float* row1 = &sS[(min(g + 1,         H_ - 1) - R0) * 160];

        #pragma unroll
        for (int j = 0; j < 5; j++) {
            const int c  = 32 * j + lane;
            const int cm = max(c - 1, 0);
            const int cp = min(c + 1, W_ - 1);

            const float a0 = row0[cm], a1 = row0[c], a2 = row0[cp];
            const float b0 = row1[cm], b1 = row1[c], b2 = row1[cp];
            const float v0 = fmaf(fy, b0 - a0, a0);
            const float v1 = fmaf(fy, b1 - a1, a1);
            const float v2 = fmaf(fy, b2 - a2, a2);
            const float da = v1 - v0;
            const float db = v2 - v1;

            float4 o;
            o.x = (fmaf(0.625f, da, v0) > 0.5f) ? 1.0f : 0.0f;
            o.y = (fmaf(0.875f, da, v0) > 0.5f) ? 1.0f : 0.0f;
            o.z = (fmaf(0.125f, db, v1) > 0.5f) ? 1.0f : 0.0f;
            o.w = (fmaf(0.375f, db, v1) > 0.5f) ? 1.0f : 0.0f;
            *reinterpret_cast<float4*>(srow + 4 * c) = o;
        }

        // make STS visible to the async proxy, then one lane issues the copy
        asm volatile("fence.proxy.async.shared::cta;" ::: "memory");
        __syncwarp();
        if (lane == 0) {
            const uint32_t s32 = (uint32_t)__cvta_generic_to_shared(srow);
            asm volatile("cp.async.bulk.global.shared::cta.bulk_group [%0], [%1], %2;"
                         :: "l"(gbase + (size_t)y * (OW_ * 4)),
                            "r"(s32), "r"((uint32_t)(ROW_FLOATS * 4))
                         : "memory");
            asm volatile("cp.async.bulk.commit_group;" ::: "memory");
        }
    }

    // full completion before kernel end (cross-kernel visibility)
    if (lane == 0)
        asm volatile("cp.async.bulk.wait_group 0;" ::: "memory");
}

// ---------------------------------------------------------------------------
extern "C" void kernel_launch(void* const* d_in, const int* in_sizes, int n_in,
                              void* d_out, int out_size)
{
    // Size-based binding (robust to order/units): det << mc < proto
    const float* mc    = nullptr;
    const float* proto = nullptr;
    const void*  det   = nullptr;

    for (int i = 0; i < n_in; i++) {
        const long long s = in_sizes[i];
        if      (s == 1075200LL || s == 4300800LL)                        mc    = (const float*)d_in[i];
        else if (s == 3276800LL || s == 13107200LL)                       proto = (const float*)d_in[i];
        else if (s == 400LL || s == 800LL || s == 1600LL || s == 3200LL)  det   = d_in[i];
    }
    if (!mc || !proto || !det) {
        int imin = 0, imax = 0;
        for (int i = 1; i < 3 && i < n_in; i++) {
            if (in_sizes[i] < in_sizes[imin]) imin = i;
            if (in_sizes[i] > in_sizes[imax]) imax = i;
        }
        const int imid = 3 - imin - imax;
        det   = d_in[imin];
        proto = (const float*)d_in[imax];
        mc    = (const float*)d_in[imid];
    }

    float* out = (float*)d_out;     // [4,100,640,640] f32 (0.0/1.0)
    (void)out_size;

    cudaFuncSetAttribute(kernelB, cudaFuncAttributeMaxDynamicSharedMemorySize, SMEMB_BYTES);

    kernelA<<<dim3(HW_ / (256 * PXT_), D_ / DT_, B_), 256>>>(mc, proto, det);
    kernelB<<<dim3(4, D_, B_), 256, SMEMB_BYTES>>>(out);
}

// round 9
// speedup vs baseline: 1.4402x; 1.0002x over previous
#include <cuda_runtime.h>
#include <math.h>
#include <stdint.h>

// Problem constants
#define B_   4
#define N_   8400
#define NM_  32
#define H_   160
#define W_   160
#define D_   100
#define HW_  (H_*W_)          // 25600
#define OW_  640
#define OH_  640

// Scratch: sigmoid masks [B][D][H][W] fp32 = 40.96 MB
__device__ float g_S[(size_t)B_ * D_ * HW_];

// Packed fp32x2 FMA (Blackwell FFMA2) — PTX-only
__device__ __forceinline__ float2 ffma2(float2 a, float2 b, float2 c) {
    union { float2 f; unsigned long long u; } ua, ub, uc, ur;
    ua.f = a; ub.f = b; uc.f = c;
    asm("fma.rn.f32x2 %0, %1, %2, %3;" : "=l"(ur.u) : "l"(ua.u), "l"(ub.u), "l"(uc.u));
    return ur.f;
}

// ---------------------------------------------------------------------------
// Kernel A: single-pass proto GEMM. Block = 256-px tile of one batch.
// Proto tile (32 x 256 = 32 KB) + all 100 coeff rows (12.8 KB) staged in smem;
// then 5 register chunks of 20 d sweep the whole tile. Proto read ONCE.
// grid (100, 4); block 256; 3 CTAs/SM.
// ---------------------------------------------------------------------------
#define PXA 256

__global__ void __launch_bounds__(256, 3)
kernelA(const float* __restrict__ mc,
        const float* __restrict__ proto,
        const void* __restrict__ det)      // int32 vs int64 detected on device
{
    const int b  = blockIdx.y;
    const int p0 = blockIdx.x * PXA;
    const int t  = threadIdx.x;

    __shared__ float sp[NM_ * PXA];        // proto tile [k][px]   32 KB
    __shared__ float sc[NM_ * D_];         // coeffs     [k][d]    12.8 KB

    // int64 det values < 2^31 -> all odd int32 words zero
    const int* d32 = (const int*)det;
    bool is64 = true;
    #pragma unroll
    for (int k = 0; k < 8; k++) if (d32[2 * k + 1] != 0) is64 = false;

    // gather coeffs: per (d, k-quad) float4 from mc, scatter to sc[k][d]
    for (int i = t; i < D_ * 8; i += 256) {
        const int d  = i >> 3;
        const int k4 = i & 7;
        long long idx = is64 ? ((const long long*)det)[b * D_ + d]
                             : (long long)d32[b * D_ + d];
        idx = min(max(idx, 0LL), (long long)(N_ - 1));
        const float4 v = *reinterpret_cast<const float4*>(
            mc + ((long long)b * N_ + idx) * NM_ + 4 * k4);
        sc[(4 * k4 + 0) * D_ + d] = v.x;
        sc[(4 * k4 + 1) * D_ + d] = v.y;
        sc[(4 * k4 + 2) * D_ + d] = v.z;
        sc[(4 * k4 + 3) * D_ + d] = v.w;
    }

    // load proto tile (float4-coalesced)
    const float* pbase = proto + (size_t)b * NM_ * HW_ + p0;
    for (int i = t; i < NM_ * PXA / 4; i += 256) {
        const int k  = i / (PXA / 4);
        const int x4 = i % (PXA / 4);
        *reinterpret_cast<float4*>(&sp[k * PXA + 4 * x4]) =
            *reinterpret_cast<const float4*>(pbase + (size_t)k * HW_ + 4 * x4);
    }
    __syncthreads();

    // 5 chunks of 20 d; FFMA2 pairs adjacent d's (one px per thread)
    for (int c5 = 0; c5 < 5; c5++) {
        const int d0 = c5 * 20;
        float2 acc[10];
        #pragma unroll
        for (int j = 0; j < 10; j++) acc[j] = make_float2(0.f, 0.f);

        #pragma unroll 8
        for (int k = 0; k < NM_; k++) {
            const float p = sp[k * PXA + t];
            const float2 pp = make_float2(p, p);
            const float4* cr = reinterpret_cast<const float4*>(&sc[k * D_ + d0]);
            #pragma unroll
            for (int j = 0; j < 5; j++) {
                const float4 c4 = cr[j];
                acc[2*j]     = ffma2(pp, make_float2(c4.x, c4.y), acc[2*j]);
                acc[2*j + 1] = ffma2(pp, make_float2(c4.z, c4.w), acc[2*j + 1]);
            }
        }

        float* gs = g_S + ((size_t)(b * D_ + d0)) * HW_ + p0 + t;
        #pragma unroll
        for (int j = 0; j < 10; j++) {
            const float s0 = 1.0f / (1.0f + __expf(-acc[j].x));
            const float s1 = 1.0f / (1.0f + __expf(-acc[j].y));
            gs[(size_t)(2*j)     * HW_] = s0;
            gs[(size_t)(2*j + 1) * HW_] = s1;
        }
    }
}

// ---------------------------------------------------------------------------
// Kernel B: 4x bilinear upsample + threshold; per-warp row pipelines with
// per-row TMA bulk stores (double-buffered, wait_group.read 1).
// Half-bands: grid (8 bands of 20 src rows, 100 d, 4 b); block 256 (8 warps);
// smem 55.0 KB -> 4 CTAs/SM (occ 50%). Warp w: rows Y0 + w + 8*ri, ri 0..9.
// ---------------------------------------------------------------------------
#define SRCROWS      22                                  // 20 + 2 halo
#define BAND_FLOATS  (SRCROWS * 160)                     // 3520 floats
#define ROW_FLOATS   OW_                                 // 640 floats = 2560 B
#define SMEMB_BYTES  ((BAND_FLOATS + 8 * 2 * ROW_FLOATS) * 4)   // 55040 B

__global__ void __launch_bounds__(256)
kernelB(float* __restrict__ out)
{
    extern __shared__ float smem[];
    float* sS = smem;                                    // [22][160] band

    const int band = blockIdx.x;                         // 0..7
    const int d    = blockIdx.y;
    const int b    = blockIdx.z;
    const int R0   = 20 * band - 1;                      // first band source row
    const int Y0   = 80 * band;

    // load source band (smem row r holds global row clamp(R0 + r))
    const float* Sg = g_S + ((size_t)(b * D_ + d)) * HW_;
    for (int i = threadIdx.x; i < SRCROWS * 40; i += 256) {
        const int r  = i / 40;
        const int x4 = i % 40;
        const int gr = min(max(R0 + r, 0), H_ - 1);
        *reinterpret_cast<float4*>(&sS[r * 160 + x4 * 4]) =
            *reinterpret_cast<const float4*>(Sg + gr * 160 + x4 * 4);
    }
    __syncthreads();

    const int w    = threadIdx.x >> 5;
    const int lane = threadIdx.x & 31;
    float* wstage = smem + BAND_FLOATS + w * (2 * ROW_FLOATS);
    const char* gbase = (const char*)(out + ((size_t)(b * D_ + d)) * (OH_ * OW_));

    for (int ri = 0; ri < 10; ri++) {
        const int y   = Y0 + w + 8 * ri;
        const int buf = ri & 1;
        float* srow = wstage + buf * ROW_FLOATS;

        // before overwriting this buffer, ensure TMA finished READING it
        if (ri >= 2) {
            if (lane == 0)
                asm volatile("cp.async.bulk.wait_group.read 1;" ::: "memory");
        }
        __syncwarp();

        const int yy = y - 2;
        const int g  = (yy >= 0) ? (yy >> 2) : -1;
        const int k  = yy - 4 * g;
        const float fy = 0.125f + 0.25f * (float)k;

        const float* row0 = &sS[(min(max(g, 0), H_ - 1) - R0) * 160];
        const float* row1 = &sS[(min(g + 1,     H_ - 1) - R0) * 160];

        #pragma unroll
        for (int j = 0; j < 5; j++) {
            const int c  = 32 * j + lane;
            const int cm = max(c - 1, 0);
            const int cp = min(c + 1, W_ - 1);

            const float a0 = row0[cm], a1 = row0[c], a2 = row0[cp];
            const float b0 = row1[cm], b1 = row1[c], b2 = row1[cp];
            const float v0 = fmaf(fy, b0 - a0, a0);
            const float v1 = fmaf(fy, b1 - a1, a1);
            const float v2 = fmaf(fy, b2 - a2, a2);
            const float da = v1 - v0;
            const float db = v2 - v1;

            float4 o;
            o.x = (fmaf(0.625f, da, v0) > 0.5f) ? 1.0f : 0.0f;
            o.y = (fmaf(0.875f, da, v0) > 0.5f) ? 1.0f : 0.0f;
            o.z = (fmaf(0.125f, db, v1) > 0.5f) ? 1.0f : 0.0f;
            o.w = (fmaf(0.375f, db, v1) > 0.5f) ? 1.0f : 0.0f;
            *reinterpret_cast<float4*>(srow + 4 * c) = o;
        }

        // make STS visible to the async proxy, then one lane issues the copy
        asm volatile("fence.proxy.async.shared::cta;" ::: "memory");
        __syncwarp();
        if (lane == 0) {
            const uint32_t s32 = (uint32_t)__cvta_generic_to_shared(srow);
            asm volatile("cp.async.bulk.global.shared::cta.bulk_group [%0], [%1], %2;"
                         :: "l"(gbase + (size_t)y * (OW_ * 4)),
                            "r"(s32), "r"((uint32_t)(ROW_FLOATS * 4))
                         : "memory");
            asm volatile("cp.async.bulk.commit_group;" ::: "memory");
        }
    }

    // full completion before kernel end
    if (lane == 0)
        asm volatile("cp.async.bulk.wait_group 0;" ::: "memory");
}

// ---------------------------------------------------------------------------
extern "C" void kernel_launch(void* const* d_in, const int* in_sizes, int n_in,
                              void* d_out, int out_size)
{
    // Size-based binding (robust to order/units): det << mc < proto
    const float* mc    = nullptr;
    const float* proto = nullptr;
    const void*  det   = nullptr;

    for (int i = 0; i < n_in; i++) {
        const long long s = in_sizes[i];
        if      (s == 1075200LL || s == 4300800LL)                        mc    = (const float*)d_in[i];
        else if (s == 3276800LL || s == 13107200LL)                       proto = (const float*)d_in[i];
        else if (s == 400LL || s == 800LL || s == 1600LL || s == 3200LL)  det   = d_in[i];
    }
    if (!mc || !proto || !det) {
        int imin = 0, imax = 0;
        for (int i = 1; i < 3 && i < n_in; i++) {
            if (in_sizes[i] < in_sizes[imin]) imin = i;
            if (in_sizes[i] > in_sizes[imax]) imax = i;
        }
        const int imid = 3 - imin - imax;
        det   = d_in[imin];
        proto = (const float*)d_in[imax];
        mc    = (const float*)d_in[imid];
    }

    float* out = (float*)d_out;     // [4,100,640,640] f32 (0.0/1.0)
    (void)out_size;

    cudaFuncSetAttribute(kernelB, cudaFuncAttributeMaxDynamicSharedMemorySize, SMEMB_BYTES);

    kernelA<<<dim3(HW_ / PXA, B_), 256>>>(mc, proto, det);
    kernelB<<<dim3(8, D_, B_), 256, SMEMB_BYTES>>>(out);
}